// round 9
// baseline (speedup 1.0000x reference)
#include <cuda_runtime.h>

#define TT 256

// Ping-pong scratch (static device arrays: no allocation anywhere).
__device__ float g_bufX[33554432];
__device__ float g_bufY[33554432];

__device__ __forceinline__ void ffma2(unsigned long long& acc,
                                      unsigned long long w,
                                      unsigned long long v) {
    asm("fma.rn.f32x2 %0, %1, %2, %0;" : "+l"(acc) : "l"(w), "l"(v));
}

// ---------------------------------------------------------------------------
// Standalone dynamics kernel (input-psp, pool, upsample layers).
// MODE 0: psp only
// MODE 2: sumpool2 + spike + psp (4-tap gather fused)
// MODE 3: bilinear-up2 + spike + psp (4-tap gather fused)
// Double-buffered register prefetch with NAMED buffers (compile-time indices).
// ---------------------------------------------------------------------------
template<int MODE>
__global__ void dyn_kernel(const float* __restrict__ in, float* __restrict__ out,
                           int H, int W, int N)
{
    int n = blockIdx.x * blockDim.x + threadIdx.x;
    if (n >= N) return;

    const float dsr  = 0.9048374180359595f;   // exp(-1/10)
    const float psc  = 0.27182818284590452f;  // e/10
    const float dref = 0.36787944117144233f;  // exp(-1)

    constexpr int S  = (MODE == 2 || MODE == 3) ? 4 : 1;
    constexpr int CH = (S == 4) ? 8 : 16;
    constexpr int F4 = CH / 4;
    constexpr int NC = TT / CH;              // even

    const float* p[S];
    float w00 = 0.f, w01 = 0.f, w10 = 0.f, w11 = 0.f;

    if (MODE == 2) {
        int x = n % W, y = (n / W) % H, bc = n / (W * H);
        int Win = 2 * W;
        const float* base = in + (((long)bc * (2 * H) + 2 * y) * Win + 2 * x) * TT;
        p[0] = base;
        p[1] = base + TT;
        p[2] = base + (long)Win * TT;
        p[3] = base + (long)(Win + 1) * TT;
    } else if (MODE == 3) {
        int x = n % W, y = (n / W) % H, bc = n / (W * H);
        int Hin = H / 2, Win = W / 2;
        int jy = y >> 1, jx = x >> 1;
        int ya, yb, xa, xb; float wya, wyb, wxa, wxb;
        if ((y & 1) == 0) { ya = (jy > 0) ? jy - 1 : 0; yb = jy; wya = 0.25f; wyb = 0.75f; }
        else              { ya = jy; yb = (jy + 1 < Hin) ? jy + 1 : Hin - 1; wya = 0.75f; wyb = 0.25f; }
        if ((x & 1) == 0) { xa = (jx > 0) ? jx - 1 : 0; xb = jx; wxa = 0.25f; wxb = 0.75f; }
        else              { xa = jx; xb = (jx + 1 < Win) ? jx + 1 : Win - 1; wxa = 0.75f; wxb = 0.25f; }
        const float* base = in + (long)bc * Hin * Win * TT;
        p[0] = base + ((long)ya * Win + xa) * TT; w00 = wya * wxa;
        p[1] = base + ((long)ya * Win + xb) * TT; w01 = wya * wxb;
        p[2] = base + ((long)yb * Win + xa) * TT; w10 = wyb * wxa;
        p[3] = base + ((long)yb * Win + xb) * TT; w11 = wyb * wxb;
    } else {
        p[0] = in + (long)n * TT;
    }

    float* ob = out + (long)n * TT;

    float g1 = 0.f, g2 = 0.f, r = 0.f;

    float4 A[S][F4], B[S][F4];

    auto load = [&](float4 (&buf)[S][F4], int c) {
        #pragma unroll
        for (int s = 0; s < S; s++)
            #pragma unroll
            for (int f = 0; f < F4; f++)
                buf[s][f] = *(const float4*)(p[s] + c * CH + f * 4);
    };

    auto compute = [&](float4 (&buf)[S][F4], int c) {
        #pragma unroll
        for (int f = 0; f < F4; f++) {
            float u[4];
            if (MODE == 2) {
                float4 a = buf[0][f], b = buf[1][f], cc = buf[2][f], d = buf[3][f];
                u[0] = 2.75f * ((a.x + b.x) + (cc.x + d.x));
                u[1] = 2.75f * ((a.y + b.y) + (cc.y + d.y));
                u[2] = 2.75f * ((a.z + b.z) + (cc.z + d.z));
                u[3] = 2.75f * ((a.w + b.w) + (cc.w + d.w));
            } else if (MODE == 3) {
                float4 a = buf[0][f], b = buf[1][f], cc = buf[2][f], d = buf[3][f];
                u[0] = w00 * a.x + w01 * b.x + w10 * cc.x + w11 * d.x;
                u[1] = w00 * a.y + w01 * b.y + w10 * cc.y + w11 * d.y;
                u[2] = w00 * a.z + w01 * b.z + w10 * cc.z + w11 * d.z;
                u[3] = w00 * a.w + w01 * b.w + w10 * cc.w + w11 * d.w;
            } else {
                float4 a = buf[0][f];
                u[0] = a.x; u[1] = a.y; u[2] = a.z; u[3] = a.w;
            }
            float o[4];
            #pragma unroll
            for (int j = 0; j < 4; j++) {
                if (MODE == 0) {
                    g1 = fmaf(dsr, g1, u[j]);
                    g2 = fmaf(dsr, g2, g1);
                    o[j] = psc * (g2 - g1);
                } else {
                    float v = u[j] + r - 10.0f;
                    float s = (v >= 0.f) ? 1.f : 0.f;
                    r = dref * (r - 20.f * s);
                    g1 = fmaf(dsr, g1, s);
                    g2 = fmaf(dsr, g2, g1);
                    o[j] = psc * (g2 - g1);
                }
            }
            *(float4*)(ob + c * CH + f * 4) = make_float4(o[0], o[1], o[2], o[3]);
        }
    };

    load(A, 0);
    for (int c = 0; c < NC; c += 2) {
        load(B, c + 1);
        compute(A, c);
        if (c + 2 < NC) load(A, c + 2);
        compute(B, c + 1);
    }
}

// ---------------------------------------------------------------------------
// Fused conv + spike/psp epilogue.  64-thread block = 2 output pixels; each
// thread owns 8 timesteps (TW=8: 4 packed u64), OCG output channels.
// Per (ic,tap) per warp: 2 LDG.128 + OCG/2 LDS.128 (broadcast weight pairs) +
// 4*OCG fma.rn.f32x2  ->  each weight LDS feeds 8 FFMA2 (2x R7), overhead/FMA
// halved. Weight table and activation staging buffer are UNIONED in smem.
// EPI = 1: spike + psp.  EPI = 4: spike only (final layer).
// ---------------------------------------------------------------------------
template<int IC, int KS, int PAD, int OCG, int EPI>
__global__ __launch_bounds__(64)
void conv_kernel(const float* __restrict__ in, const float* __restrict__ wgt,
                 float* __restrict__ out, int H, int W, int OC)
{
    constexpr int SW_BYTES = IC * KS * KS * OCG * 8;
    constexpr int SA_BYTES = 2 * OCG * 260 * 4;
    constexpr int SM_BYTES = SW_BYTES > SA_BYTES ? SW_BYTES : SA_BYTES;
    __shared__ __align__(16) unsigned char smem_raw[SM_BYTES];
    unsigned long long* sw = (unsigned long long*)smem_raw;
    float* sa = (float*)smem_raw;           // rows: [2*OCG][260]

    int px   = threadIdx.x >> 5;            // pixel within block (0,1)
    int lane = threadIdx.x & 31;
    int t    = lane * 8;

    int pix = blockIdx.x * 2 + px;
    int x = pix % W, y = (pix / W) % H, b = pix / (W * H);
    int oc0 = blockIdx.y * OCG;

    for (int i = threadIdx.x; i < IC * KS * KS * OCG; i += 64) {
        int k = i / OCG, o = i % OCG;
        unsigned u = __float_as_uint(wgt[(long)(oc0 + o) * IC * KS * KS + k]);
        sw[i] = ((unsigned long long)u << 32) | u;
    }
    __syncthreads();

    unsigned long long acc[OCG][4];
    #pragma unroll
    for (int o = 0; o < OCG; o++)
        #pragma unroll
        for (int q = 0; q < 4; q++) acc[o][q] = 0ull;

    const long planeT = (long)H * W * TT;
    const float* inb = in + (long)b * IC * planeT + t;

    #pragma unroll
    for (int kh = 0; kh < KS; kh++) {
        int yy = y + kh - PAD;
        if (yy < 0 || yy >= H) continue;
        #pragma unroll
        for (int kw = 0; kw < KS; kw++) {
            int xx = x + kw - PAD;
            if (xx < 0 || xx >= W) continue;
            const float* p = inb + ((long)yy * W + xx) * TT;
            int kidx = kh * KS + kw;
            #pragma unroll 2
            for (int ic = 0; ic < IC; ic++) {
                const ulonglong2* pv = (const ulonglong2*)(p + (long)ic * planeT);
                ulonglong2 v0 = pv[0];
                ulonglong2 v1 = pv[1];
                const unsigned long long* swp = &sw[(ic * KS * KS + kidx) * OCG];
                if constexpr (OCG % 2 == 0) {
                    #pragma unroll
                    for (int o = 0; o < OCG; o += 2) {
                        ulonglong2 wv = *(const ulonglong2*)(swp + o);
                        ffma2(acc[o    ][0], wv.x, v0.x);
                        ffma2(acc[o    ][1], wv.x, v0.y);
                        ffma2(acc[o    ][2], wv.x, v1.x);
                        ffma2(acc[o    ][3], wv.x, v1.y);
                        ffma2(acc[o + 1][0], wv.y, v0.x);
                        ffma2(acc[o + 1][1], wv.y, v0.y);
                        ffma2(acc[o + 1][2], wv.y, v1.x);
                        ffma2(acc[o + 1][3], wv.y, v1.y);
                    }
                } else {
                    #pragma unroll
                    for (int o = 0; o < OCG; o++) {
                        unsigned long long wv = swp[o];
                        ffma2(acc[o][0], wv, v0.x);
                        ffma2(acc[o][1], wv, v0.y);
                        ffma2(acc[o][2], wv, v1.x);
                        ffma2(acc[o][3], wv, v1.y);
                    }
                }
            }
        }
    }

    // All threads done reading sw -> safe to overwrite with sa.
    __syncthreads();

    #pragma unroll
    for (int o = 0; o < OCG; o++) {
        float* sap = sa + (px * OCG + o) * 260 + t;
        *(float2*)(sap    ) = *(float2*)&acc[o][0];
        *(float2*)(sap + 2) = *(float2*)&acc[o][1];
        *(float2*)(sap + 4) = *(float2*)&acc[o][2];
        *(float2*)(sap + 6) = *(float2*)&acc[o][3];
    }
    __syncthreads();

    // Per-(pixel,channel) serial recurrence over T (2*OCG threads; hidden
    // under the conv mainloops of co-resident blocks).
    if (threadIdx.x < 2 * OCG) {
        const float dsr  = 0.9048374180359595f;
        const float psc  = 0.27182818284590452f;
        const float dref = 0.36787944117144233f;
        float* row = sa + threadIdx.x * 260;
        float g1 = 0.f, g2 = 0.f, r = 0.f;
        float4 nxt = *(float4*)row;
        for (int tt = 0; tt < TT; tt += 4) {
            float4 a = nxt;
            if (tt + 4 < TT) nxt = *(float4*)(row + tt + 4);
            float u[4] = {a.x, a.y, a.z, a.w};
            float o4[4];
            #pragma unroll
            for (int j = 0; j < 4; j++) {
                float v = u[j] + r - 10.0f;
                float s = (v >= 0.f) ? 1.f : 0.f;
                r = dref * (r - 20.f * s);
                if (EPI == 4) {
                    o4[j] = s;
                } else {
                    g1 = fmaf(dsr, g1, s);
                    g2 = fmaf(dsr, g2, g1);
                    o4[j] = psc * (g2 - g1);
                }
            }
            *(float4*)(row + tt) = make_float4(o4[0], o4[1], o4[2], o4[3]);
        }
    }
    __syncthreads();

    // Coalesced float4 stores of the PSP (or spike) tensor.
    float* ob = out + ((long)b * OC + oc0) * planeT + ((long)y * W + x) * TT + t;
    #pragma unroll
    for (int o = 0; o < OCG; o++) {
        const float* sap = sa + (px * OCG + o) * 260 + t;
        *(float4*)(ob + (long)o * planeT    ) = *(const float4*)(sap);
        *(float4*)(ob + (long)o * planeT + 4) = *(const float4*)(sap + 4);
    }
}

// ---------------------------------------------------------------------------
// 10 launches, ping-pong X<->Y.
// ---------------------------------------------------------------------------
extern "C" void kernel_launch(void* const* d_in, const int* in_sizes, int n_in,
                              void* d_out, int out_size)
{
    const float* inp = (const float*)d_in[0];  // [4,1,32,32,256]
    const float* w1  = (const float*)d_in[1];  // [16,1,5,5,1]
    const float* w2  = (const float*)d_in[2];  // [32,16,3,3,1]
    const float* w3  = (const float*)d_in[3];  // [64,32,3,3,1]
    const float* w4  = (const float*)d_in[4];  // [32,64,3,3,1]
    const float* wo  = (const float*)d_in[5];  // [1,32,1,1,1]
    float* out = (float*)d_out;

    float *X, *Y;
    cudaGetSymbolAddress((void**)&X, g_bufX);
    cudaGetSymbolAddress((void**)&Y, g_bufY);

    // P0 = psp(input) -> X        (N=4096)
    dyn_kernel<0><<<128, 32>>>(inp, X, 32, 32, 4096);

    // P1 = spike/psp(conv1(P0)) -> Y      OCG=8
    conv_kernel<1, 5, 2, 8, 1><<<dim3(2048, 2), 64>>>(X, w1, Y, 32, 32, 16);

    // P2 = pool+spike+psp(P1) -> X   [4,16,16,16]
    dyn_kernel<2><<<256, 64>>>(Y, X, 16, 16, 16384);

    // P3 = spike/psp(conv2(P2)) -> Y      OCG=8
    conv_kernel<16, 3, 1, 8, 1><<<dim3(512, 4), 64>>>(X, w2, Y, 16, 16, 32);

    // P4 = pool+spike+psp(P3) -> X   [4,32,8,8]
    dyn_kernel<2><<<256, 32>>>(Y, X, 8, 8, 8192);

    // P5 = spike/psp(conv3(P4)) -> Y      OCG=8
    conv_kernel<32, 3, 1, 8, 1><<<dim3(128, 8), 64>>>(X, w3, Y, 8, 8, 64);

    // P6 = up+spike+psp(P5) -> X   [4,64,16,16]
    dyn_kernel<3><<<512, 128>>>(Y, X, 16, 16, 65536);

    // P7 = spike/psp(conv4(P6)) -> Y      OCG=4
    conv_kernel<64, 3, 1, 4, 1><<<dim3(512, 8), 64>>>(X, w4, Y, 16, 16, 32);

    // P8 = up+spike+psp(P7) -> X   [4,32,32,32]
    dyn_kernel<3><<<1024, 128>>>(Y, X, 32, 32, 131072);

    // out = spike(conv_out(P8))
    conv_kernel<32, 1, 0, 1, 4><<<dim3(2048, 1), 64>>>(X, wo, out, 32, 32, 1);
}